// round 5
// baseline (speedup 1.0000x reference)
#include <cuda_runtime.h>
#include <cuda_bf16.h>
#include <math.h>

// ---------------- problem constants ----------------
#define BB     32
#define NP     192
#define CC     128
#define NS     36
#define MID    64
#define FCH    128
#define NSAMP  (BB * NP)        // 6144
#define KTOT   (CC * NS)        // 4608
#define L250   250
#define EPS    1e-5f

// ---------------- scratch (device globals; no allocation allowed) ----------------
__device__ float g_cat[(size_t)NSAMP * 192 * NS];     // concat of 3 level-conv outputs (6144,192,36)
__device__ float g_catout[(size_t)NSAMP * CC * NS];   // catconv output (6144,128,36)
__device__ float g_roi[(size_t)NSAMP * FCH];          // fc+LN+ReLU output (6144,128)
__device__ float g_k[(size_t)BB * L250 * CC];         // key, layout (b,l,c)
__device__ float g_v[(size_t)BB * L250 * CC];         // val, layout (b,l,c)

// =====================================================================
// Kernel 1: per-level conv9 (Cin=128 -> Cout=64) + BN + ReLU -> g_cat
// grid: (6144/4, 3 levels), block 256 = 4 samples x (16 o-groups x 4 s-groups)
// thread tile: 4 out-channels x 9 positions
// =====================================================================
__global__ __launch_bounds__(256) void conv_level_kernel(
    const float* __restrict__ x0, const float* __restrict__ x1, const float* __restrict__ x2,
    const float* __restrict__ conv_w, const float* __restrict__ conv_g, const float* __restrict__ conv_b,
    const float* __restrict__ conv_m, const float* __restrict__ conv_v)
{
    __shared__ float Ws[64 * 145];        // 64 o x (16 c x 9 t), o-stride padded to 145 (bank-conflict free)
    __shared__ float Xs[4][16 * 44];      // 4 samples x 16 c x (36 + 8 halo)

    const int lvl = blockIdx.y;
    const int n0  = blockIdx.x * 4;
    const float* x = (lvl == 0) ? x0 : ((lvl == 1) ? x1 : x2);
    const int tid = threadIdx.x;

    // zero the halo once (interior is overwritten every chunk)
    for (int i = tid; i < 4 * 16 * 8; i += 256) {
        int smp = i >> 7;
        int r   = i & 127;
        int ci  = r >> 3;
        int p   = r & 7;
        int pp  = (p < 4) ? p : (36 + p);   // 0..3 and 40..43
        Xs[smp][ci * 44 + pp] = 0.f;
    }

    const int smp = tid >> 6;
    const int t64 = tid & 63;
    const int sg  = t64 & 3;
    const int og  = t64 >> 2;
    const int s0  = sg * 9;
    const int o0  = og * 4;

    float acc[4][9];
#pragma unroll
    for (int i = 0; i < 4; i++)
#pragma unroll
        for (int j = 0; j < 9; j++) acc[i][j] = 0.f;

    for (int cc = 0; cc < 128; cc += 16) {
        __syncthreads();
        // load W chunk: 64 o x 16 c x 9 t = 9216
        for (int i = tid; i < 9216; i += 256) {
            int o = i / 144;
            int r = i - o * 144;                        // r = c_local*9 + t
            Ws[o * 145 + r] = conv_w[((lvl * 64 + o) * 128 + cc) * 9 + r];
        }
        // load X chunk: 4 smp x 16 c x 36 s
        for (int i = tid; i < 4 * 16 * 36; i += 256) {
            int sm = i / 576;
            int r  = i - sm * 576;
            int c  = r / 36;
            int s  = r - c * 36;
            Xs[sm][c * 44 + 4 + s] = x[(((size_t)(n0 + sm)) * 128 + cc + c) * 36 + s];
        }
        __syncthreads();

        for (int ci = 0; ci < 16; ci++) {
            float xv[17];
#pragma unroll
            for (int p = 0; p < 17; p++) xv[p] = Xs[smp][ci * 44 + s0 + p];
#pragma unroll
            for (int t = 0; t < 9; t++) {
                float w0 = Ws[(o0 + 0) * 145 + ci * 9 + t];
                float w1 = Ws[(o0 + 1) * 145 + ci * 9 + t];
                float w2 = Ws[(o0 + 2) * 145 + ci * 9 + t];
                float w3 = Ws[(o0 + 3) * 145 + ci * 9 + t];
#pragma unroll
                for (int j = 0; j < 9; j++) {
                    float xx = xv[t + j];
                    acc[0][j] += w0 * xx;
                    acc[1][j] += w1 * xx;
                    acc[2][j] += w2 * xx;
                    acc[3][j] += w3 * xx;
                }
            }
        }
    }

    // BN + ReLU, write into concat buffer at channel offset lvl*64
#pragma unroll
    for (int i = 0; i < 4; i++) {
        int o  = o0 + i;
        int gc = lvl * 64 + o;
        float sc = conv_g[gc] * rsqrtf(conv_v[gc] + EPS);
        float bi = conv_b[gc] - conv_m[gc] * sc;
        float* outp = &g_cat[(((size_t)(n0 + smp)) * 192 + gc) * 36 + s0];
#pragma unroll
        for (int j = 0; j < 9; j++) {
            float vv = acc[i][j] * sc + bi;
            outp[j] = vv > 0.f ? vv : 0.f;
        }
    }
}

// =====================================================================
// Kernel 2: catconv9 (Cin=192 -> Cout=128) + BN + ReLU -> g_catout
// grid: 6144/2, block 256 = 2 samples x (32 o-groups x 4 s-groups)
// =====================================================================
__global__ __launch_bounds__(256) void catconv_kernel(
    const float* __restrict__ cat_w, const float* __restrict__ cat_g, const float* __restrict__ cat_b,
    const float* __restrict__ cat_m, const float* __restrict__ cat_v)
{
    __shared__ float Ws[128 * 73];        // 128 o x (8 c x 9 t), padded stride 73
    __shared__ float Xs[2][8 * 44];

    const int n0  = blockIdx.x * 2;
    const int tid = threadIdx.x;

    if (tid < 128) {
        int smp = tid >> 6;
        int r   = tid & 63;
        int ci  = r >> 3;
        int p   = r & 7;
        int pp  = (p < 4) ? p : (36 + p);
        Xs[smp][ci * 44 + pp] = 0.f;
    }

    const int smp  = tid >> 7;
    const int t128 = tid & 127;
    const int sg   = t128 & 3;
    const int og   = t128 >> 2;          // 0..31
    const int s0   = sg * 9;
    const int o0   = og * 4;

    float acc[4][9];
#pragma unroll
    for (int i = 0; i < 4; i++)
#pragma unroll
        for (int j = 0; j < 9; j++) acc[i][j] = 0.f;

    for (int cc = 0; cc < 192; cc += 8) {
        __syncthreads();
        for (int i = tid; i < 128 * 72; i += 256) {
            int o = i / 72;
            int r = i - o * 72;
            Ws[o * 73 + r] = cat_w[(o * 192 + cc) * 9 + r];
        }
        for (int i = tid; i < 2 * 8 * 36; i += 256) {
            int sm = i / 288;
            int r  = i - sm * 288;
            int c  = r / 36;
            int s  = r - c * 36;
            Xs[sm][c * 44 + 4 + s] = g_cat[(((size_t)(n0 + sm)) * 192 + cc + c) * 36 + s];
        }
        __syncthreads();

        for (int ci = 0; ci < 8; ci++) {
            float xv[17];
#pragma unroll
            for (int p = 0; p < 17; p++) xv[p] = Xs[smp][ci * 44 + s0 + p];
#pragma unroll
            for (int t = 0; t < 9; t++) {
                float w0 = Ws[(o0 + 0) * 73 + ci * 9 + t];
                float w1 = Ws[(o0 + 1) * 73 + ci * 9 + t];
                float w2 = Ws[(o0 + 2) * 73 + ci * 9 + t];
                float w3 = Ws[(o0 + 3) * 73 + ci * 9 + t];
#pragma unroll
                for (int j = 0; j < 9; j++) {
                    float xx = xv[t + j];
                    acc[0][j] += w0 * xx;
                    acc[1][j] += w1 * xx;
                    acc[2][j] += w2 * xx;
                    acc[3][j] += w3 * xx;
                }
            }
        }
    }

#pragma unroll
    for (int i = 0; i < 4; i++) {
        int o = o0 + i;
        float sc = cat_g[o] * rsqrtf(cat_v[o] + EPS);
        float bi = cat_b[o] - cat_m[o] * sc;
        float* outp = &g_catout[(((size_t)(n0 + smp)) * 128 + o) * 36 + s0];
#pragma unroll
        for (int j = 0; j < 9; j++) {
            float vv = acc[i][j] * sc + bi;
            outp[j] = vv > 0.f ? vv : 0.f;
        }
    }
}

// =====================================================================
// Kernel 3: fc (M=6144,N=128,K=4608) + bias + LayerNorm + ReLU -> g_roi
// grid 192 (32 rows each), block 256, 4x4 register tile
// =====================================================================
__global__ __launch_bounds__(256) void fc_ln_kernel(
    const float* __restrict__ fc_w, const float* __restrict__ fc_b,
    const float* __restrict__ ln_g, const float* __restrict__ ln_b)
{
    __shared__ float As[32 * 33];
    __shared__ float Bs[128 * 33];
    __shared__ float Hs[32 * 129];

    const int mb  = blockIdx.x * 32;
    const int tid = threadIdx.x;
    const int tn  = tid & 31;
    const int tm  = tid >> 5;
    const int n0  = tn * 4;
    const int m0  = tm * 4;

    float acc[4][4];
#pragma unroll
    for (int i = 0; i < 4; i++)
#pragma unroll
        for (int j = 0; j < 4; j++) acc[i][j] = 0.f;

    for (int kk = 0; kk < KTOT; kk += 32) {
        __syncthreads();
        for (int i = tid; i < 32 * 32; i += 256) {
            int m = i >> 5, k = i & 31;
            As[m * 33 + k] = g_catout[((size_t)(mb + m)) * KTOT + kk + k];
        }
        for (int i = tid; i < 128 * 32; i += 256) {
            int f = i >> 5, k = i & 31;
            Bs[f * 33 + k] = fc_w[(size_t)f * KTOT + kk + k];
        }
        __syncthreads();
#pragma unroll
        for (int k = 0; k < 32; k++) {
            float a0 = As[(m0 + 0) * 33 + k];
            float a1 = As[(m0 + 1) * 33 + k];
            float a2 = As[(m0 + 2) * 33 + k];
            float a3 = As[(m0 + 3) * 33 + k];
            float b0 = Bs[(n0 + 0) * 33 + k];
            float b1 = Bs[(n0 + 1) * 33 + k];
            float b2 = Bs[(n0 + 2) * 33 + k];
            float b3 = Bs[(n0 + 3) * 33 + k];
            acc[0][0] += a0 * b0; acc[0][1] += a0 * b1; acc[0][2] += a0 * b2; acc[0][3] += a0 * b3;
            acc[1][0] += a1 * b0; acc[1][1] += a1 * b1; acc[1][2] += a1 * b2; acc[1][3] += a1 * b3;
            acc[2][0] += a2 * b0; acc[2][1] += a2 * b1; acc[2][2] += a2 * b2; acc[2][3] += a2 * b3;
            acc[3][0] += a3 * b0; acc[3][1] += a3 * b1; acc[3][2] += a3 * b2; acc[3][3] += a3 * b3;
        }
    }

    __syncthreads();
#pragma unroll
    for (int i = 0; i < 4; i++)
#pragma unroll
        for (int j = 0; j < 4; j++)
            Hs[(m0 + i) * 129 + n0 + j] = acc[i][j] + fc_b[n0 + j];
    __syncthreads();

    if (tid < 32) {
        int m = tid;
        float mu = 0.f;
        for (int f = 0; f < 128; f++) mu += Hs[m * 129 + f];
        mu *= (1.f / 128.f);
        float var = 0.f;
        for (int f = 0; f < 128; f++) {
            float d = Hs[m * 129 + f] - mu;
            var += d * d;
        }
        var *= (1.f / 128.f);
        float inv = rsqrtf(var + EPS);
        for (int f = 0; f < 128; f++) {
            float vv = (Hs[m * 129 + f] - mu) * inv * ln_g[f] + ln_b[f];
            g_roi[((size_t)(mb + m)) * 128 + f] = vv > 0.f ? vv : 0.f;
        }
    }
}

// =====================================================================
// Kernel 4: key/val ONLY at the 250 nearest-subsampled points.
// nearest resize 40x100 -> 10x25 is exact (h=4i, w=4j).
// grid (32 b, 10 l-tiles), block 256.
// =====================================================================
__global__ __launch_bounds__(256) void keyval_kernel(
    const float* __restrict__ fmap,
    const float* __restrict__ key_w, const float* __restrict__ key_g, const float* __restrict__ key_beta,
    const float* __restrict__ key_m, const float* __restrict__ key_v,
    const float* __restrict__ val_w, const float* __restrict__ val_b)
{
    __shared__ float Xs[128][26];

    const int b   = blockIdx.x;
    const int l0  = blockIdx.y * 25;
    const int tid = threadIdx.x;

    for (int i = tid; i < 128 * 25; i += 256) {
        int c = i / 25;
        int l = i - c * 25;
        int L = l0 + l;
        int h = (L / 25) * 4;
        int w = (L % 25) * 4;
        Xs[c][l] = fmap[(((size_t)b * 128 + c) * 40 + h) * 100 + w];
    }
    __syncthreads();

    const int o     = tid & 127;
    const int which = tid >> 7;     // 0 -> key path, 1 -> val path
    const float* W  = which ? val_w : key_w;
    float sc, bi;
    if (which == 0) {
        sc = key_g[o] * rsqrtf(key_v[o] + EPS);
        bi = key_beta[o] - key_m[o] * sc;
    } else {
        sc = 1.f;
        bi = val_b[o];
    }

    float acc[25];
#pragma unroll
    for (int l = 0; l < 25; l++) acc[l] = 0.f;
    for (int c = 0; c < 128; c++) {
        float w = W[o * 128 + c];
#pragma unroll
        for (int l = 0; l < 25; l++) acc[l] += w * Xs[c][l];
    }

    if (which == 0) {
        for (int l = 0; l < 25; l++) {
            float vv = acc[l] * sc + bi;
            g_k[((size_t)b * L250 + l0 + l) * 128 + o] = vv > 0.f ? vv : 0.f;
        }
    } else {
        for (int l = 0; l < 25; l++) {
            g_v[((size_t)b * L250 + l0 + l) * 128 + o] = acc[l] + bi;
        }
    }
}

// =====================================================================
// Kernel 5: attention: q = relu(roi*qw+qb); softmax(q.k / sqrt(C)); ctx = p.v;
// out = roi + ctx*gate_w + gate_b.  grid (192 n, 32 b), block 256.
// =====================================================================
__global__ __launch_bounds__(256) void attn_kernel(
    const float* __restrict__ q_w, const float* __restrict__ q_b,
    const float* __restrict__ gate_w, const float* __restrict__ gate_b,
    float* __restrict__ out)
{
    __shared__ float qs[128];
    __shared__ float ros[128];
    __shared__ float sc[256];
    __shared__ float red[16];
    __shared__ float ctxs[2][128];

    const int n   = blockIdx.x;
    const int b   = blockIdx.y;
    const int tid = threadIdx.x;
    const size_t row = ((size_t)b * NP + n) * 128;

    if (tid < 128) {
        float r = g_roi[row + tid];
        ros[tid] = r;
        float qq = r * q_w[n] + q_b[n];
        qs[tid] = qq > 0.f ? qq : 0.f;
    }
    __syncthreads();

    const int warp = tid >> 5;
    const int lane = tid & 31;
    const float scale = 0.08838834764831845f;   // 128^-0.5

    for (int l = warp; l < L250; l += 8) {
        const float* kp = &g_k[((size_t)b * L250 + l) * 128];
        float d = 0.f;
#pragma unroll
        for (int c0 = 0; c0 < 128; c0 += 32) d += qs[c0 + lane] * kp[c0 + lane];
#pragma unroll
        for (int off = 16; off > 0; off >>= 1) d += __shfl_xor_sync(0xffffffffu, d, off);
        if (lane == 0) sc[l] = d * scale;
    }
    __syncthreads();

    // block max
    float m = -1e30f;
    for (int l = tid; l < L250; l += 256) m = fmaxf(m, sc[l]);
#pragma unroll
    for (int off = 16; off > 0; off >>= 1) m = fmaxf(m, __shfl_xor_sync(0xffffffffu, m, off));
    if (lane == 0) red[warp] = m;
    __syncthreads();
    if (tid < 8) {
        float mm = red[tid];
#pragma unroll
        for (int off = 4; off > 0; off >>= 1) mm = fmaxf(mm, __shfl_xor_sync(0xffu, mm, off));
        if (tid == 0) red[0] = mm;
    }
    __syncthreads();
    m = red[0];

    // exp + block sum (scores left unnormalized; fold 1/sum into ctx)
    float s = 0.f;
    for (int l = tid; l < L250; l += 256) {
        float e = __expf(sc[l] - m);
        sc[l] = e;
        s += e;
    }
#pragma unroll
    for (int off = 16; off > 0; off >>= 1) s += __shfl_xor_sync(0xffffffffu, s, off);
    if (lane == 0) red[8 + warp] = s;
    __syncthreads();
    if (tid < 8) {
        float ss = red[8 + tid];
#pragma unroll
        for (int off = 4; off > 0; off >>= 1) ss += __shfl_xor_sync(0xffu, ss, off);
        if (tid == 0) red[8] = ss;
    }
    __syncthreads();
    const float inv = 1.f / red[8];

    // ctx
    const int c    = tid & 127;
    const int half = tid >> 7;
    float a = 0.f;
    for (int l = half; l < L250; l += 2)
        a += sc[l] * g_v[((size_t)b * L250 + l) * 128 + c];
    ctxs[half][c] = a;
    __syncthreads();

    if (tid < 128) {
        float ctx = (ctxs[0][tid] + ctxs[1][tid]) * inv;
        out[row + tid] = ros[tid] + ctx * gate_w[n] + gate_b[n];
    }
}

// =====================================================================
extern "C" void kernel_launch(void* const* d_in, const int* in_sizes, int n_in,
                              void* d_out, int out_size)
{
    const float* roi0   = (const float*)d_in[0];
    const float* roi1   = (const float*)d_in[1];
    const float* roi2   = (const float*)d_in[2];
    const float* fmap   = (const float*)d_in[3];
    const float* conv_w = (const float*)d_in[4];
    const float* conv_g = (const float*)d_in[5];
    const float* conv_b = (const float*)d_in[6];
    const float* conv_m = (const float*)d_in[7];
    const float* conv_v = (const float*)d_in[8];
    const float* cat_w  = (const float*)d_in[9];
    const float* cat_g  = (const float*)d_in[10];
    const float* cat_b  = (const float*)d_in[11];
    const float* cat_m  = (const float*)d_in[12];
    const float* cat_v  = (const float*)d_in[13];
    const float* fc_w   = (const float*)d_in[14];
    const float* fc_b   = (const float*)d_in[15];
    const float* ln_g   = (const float*)d_in[16];
    const float* ln_b   = (const float*)d_in[17];
    const float* key_w  = (const float*)d_in[18];
    const float* key_g  = (const float*)d_in[19];
    const float* key_be = (const float*)d_in[20];
    const float* key_m  = (const float*)d_in[21];
    const float* key_v  = (const float*)d_in[22];
    const float* q_w    = (const float*)d_in[23];
    const float* q_b    = (const float*)d_in[24];
    const float* val_w  = (const float*)d_in[25];
    const float* val_b  = (const float*)d_in[26];
    const float* gate_w = (const float*)d_in[27];
    const float* gate_b = (const float*)d_in[28];
    // d_in[29] = layer_index (unused; cat_w is already the selected layer's weights)

    float* out = (float*)d_out;

    conv_level_kernel<<<dim3(NSAMP / 4, 3), 256>>>(roi0, roi1, roi2,
                                                   conv_w, conv_g, conv_b, conv_m, conv_v);
    catconv_kernel<<<NSAMP / 2, 256>>>(cat_w, cat_g, cat_b, cat_m, cat_v);
    fc_ln_kernel<<<NSAMP / 32, 256>>>(fc_w, fc_b, ln_g, ln_b);
    keyval_kernel<<<dim3(BB, 10), 256>>>(fmap, key_w, key_g, key_be, key_m, key_v, val_w, val_b);
    attn_kernel<<<dim3(NP, BB), 256>>>(q_w, q_b, gate_w, gate_b, out);
}

// round 9
// speedup vs baseline: 1.4528x; 1.4528x over previous
#include <cuda_runtime.h>
#include <cuda_bf16.h>
#include <math.h>
#include <stdint.h>

// ---------------- problem constants ----------------
#define BB     32
#define NP     192
#define CC     128
#define NS     36
#define MID    64
#define FCH    128
#define NSAMP  (BB * NP)        // 6144
#define KTOT   (CC * NS)        // 4608
#define L250   250
#define EPS    1e-5f

// ---------------- scratch (device globals; no allocation allowed) ----------------
__device__ float g_cat[(size_t)NSAMP * 192 * NS];     // concat of 3 level-conv outputs
__device__ float g_catout[(size_t)NSAMP * CC * NS];   // catconv output
__device__ float g_roi[(size_t)NSAMP * FCH];          // fc output h (pre-LN; LN folded into attn)
__device__ float g_k[(size_t)BB * L250 * CC];         // key (b,l,c)
__device__ float g_v[(size_t)BB * L250 * CC];         // val (b,l,c)
// pre-transposed tf32 weights: [(c*9+t)][o] contiguous
__device__ uint32_t g_wlvl[3 * 128 * 9 * 64];         // per level
__device__ uint32_t g_wcat[192 * 9 * 128];

// ---------------- tf32 helpers ----------------
__device__ __forceinline__ uint32_t f2tf(float f) {
    uint32_t u;
    asm("cvt.rna.tf32.f32 %0, %1;" : "=r"(u) : "f"(f));
    return u;
}

__device__ __forceinline__ void mma_tf32(float c[4], const uint32_t a[4], const uint32_t b[2]) {
    asm volatile(
        "mma.sync.aligned.m16n8k8.row.col.f32.tf32.tf32.f32 "
        "{%0,%1,%2,%3}, {%4,%5,%6,%7}, {%8,%9}, {%0,%1,%2,%3};\n"
        : "+f"(c[0]), "+f"(c[1]), "+f"(c[2]), "+f"(c[3])
        : "r"(a[0]), "r"(a[1]), "r"(a[2]), "r"(a[3]), "r"(b[0]), "r"(b[1]));
}

// =====================================================================
// Kernel 0: one-time weight transpose + tf32 convert.
// conv: 3*64*128*9 = 221184 elems; cat: 128*192*9 = 221184 elems.
// =====================================================================
__global__ __launch_bounds__(256) void prep_w_kernel(
    const float* __restrict__ conv_w, const float* __restrict__ cat_w)
{
    int i = blockIdx.x * 256 + threadIdx.x;
    if (i < 3 * 128 * 9 * 64) {
        int lvl = i / (128 * 9 * 64);
        int r   = i - lvl * (128 * 9 * 64);
        int row = r >> 6;           // c*9 + t
        int o   = r & 63;
        int c   = row / 9, t = row - c * 9;
        g_wlvl[i] = f2tf(conv_w[((lvl * 64 + o) * 128 + c) * 9 + t]);
    }
    if (i < 192 * 9 * 128) {
        int row = i >> 7;           // c*9 + t
        int o   = i & 127;
        int c   = row / 9, t = row - c * 9;
        g_wcat[i] = f2tf(cat_w[(o * 192 + c) * 9 + t]);
    }
}

// =====================================================================
// Kernel 1: per-level conv9 (128->64) + BN + ReLU via tf32 MMA.
// grid (6144/8, 3), block 256 = 8 warps, one sample per warp.
// Warp computes O[64, 40] (cols 36..39 padded/discarded).
// Conv = 9 shifted GEMMs: for t in 0..8, K=channels.
// =====================================================================
__global__ __launch_bounds__(256, 1) void conv_level_mma(
    const float* __restrict__ x0, const float* __restrict__ x1, const float* __restrict__ x2,
    const float* __restrict__ conv_g, const float* __restrict__ conv_b,
    const float* __restrict__ conv_m, const float* __restrict__ conv_v)
{
    __shared__ uint32_t Ws[72 * 72];            // [(c_local*9+t)][o], stride 72 (≡8 mod 32)
    __shared__ uint32_t Xs[8 * 8 * 44 + 8];     // [smp][c_local][44], stride 44 (≡12 mod 32)

    const int lvl   = blockIdx.y;
    const int n0    = blockIdx.x * 8;
    const float* __restrict__ x = (lvl == 0) ? x0 : ((lvl == 1) ? x1 : x2);
    const int tid   = threadIdx.x;
    const int warp  = tid >> 5;
    const int lane  = tid & 31;
    const int group = lane >> 2;    // 0..7
    const int tg    = lane & 3;     // 0..3
    const int smp   = warp;         // sample within block

    // zero Xs once: halos (cols 0-3, 40-43) + tail pad stay zero across chunks
    for (int i = tid; i < 8 * 8 * 44 + 8; i += 256) Xs[i] = 0u;

    float acc[4][5][4];
#pragma unroll
    for (int mi = 0; mi < 4; mi++)
#pragma unroll
        for (int ni = 0; ni < 5; ni++)
#pragma unroll
            for (int j = 0; j < 4; j++) acc[mi][ni][j] = 0.f;

    const uint32_t* __restrict__ wl = &g_wlvl[lvl * (128 * 9 * 64)];

    for (int cb = 0; cb < 128; cb += 8) {
        __syncthreads();
        // Ws chunk: 72 rows x 64 o, gmem fully contiguous, smem stride-1 stores
        {
            const uint32_t* src = wl + (cb * 9) * 64;
            for (int i = tid; i < 72 * 64; i += 256) {
                int row = i >> 6, o = i & 63;
                Ws[row * 72 + o] = src[i];
            }
        }
        // Xs chunk: 8 smp x 8 c x 36 (interior cols 4..39)
        for (int i = tid; i < 8 * 8 * 36; i += 256) {
            int sm = i / 288;
            int r  = i - sm * 288;
            int ci = r / 36;
            int s  = r - ci * 36;
            Xs[(sm * 8 + ci) * 44 + 4 + s] =
                f2tf(x[(((size_t)(n0 + sm)) * 128 + cb + ci) * 36 + s]);
        }
        __syncthreads();

#pragma unroll
        for (int t = 0; t < 9; t++) {
            uint32_t a[4][4];
#pragma unroll
            for (int mi = 0; mi < 4; mi++) {
                int o = mi * 16 + group;
                a[mi][0] = Ws[(tg * 9 + t) * 72 + o];
                a[mi][1] = Ws[(tg * 9 + t) * 72 + o + 8];
                a[mi][2] = Ws[((tg + 4) * 9 + t) * 72 + o];
                a[mi][3] = Ws[((tg + 4) * 9 + t) * 72 + o + 8];
            }
            uint32_t b[5][2];
#pragma unroll
            for (int ni = 0; ni < 5; ni++) {
                int idx = (smp * 8 + tg) * 44 + ni * 8 + group + t;
                b[ni][0] = Xs[idx];
                b[ni][1] = Xs[idx + 4 * 44];
            }
#pragma unroll
            for (int mi = 0; mi < 4; mi++)
#pragma unroll
                for (int ni = 0; ni < 5; ni++)
                    mma_tf32(acc[mi][ni], a[mi], b[ni]);
        }
    }

    // epilogue: BN + ReLU -> g_cat
#pragma unroll
    for (int mi = 0; mi < 4; mi++) {
        int o0  = mi * 16 + group;
        int gc0 = lvl * 64 + o0, gc1 = gc0 + 8;
        float sc0 = conv_g[gc0] * rsqrtf(conv_v[gc0] + EPS);
        float bi0 = conv_b[gc0] - conv_m[gc0] * sc0;
        float sc1 = conv_g[gc1] * rsqrtf(conv_v[gc1] + EPS);
        float bi1 = conv_b[gc1] - conv_m[gc1] * sc1;
        float* r0 = &g_cat[(((size_t)(n0 + smp)) * 192 + gc0) * 36];
        float* r1 = &g_cat[(((size_t)(n0 + smp)) * 192 + gc1) * 36];
#pragma unroll
        for (int ni = 0; ni < 5; ni++) {
            int p0 = ni * 8 + 2 * tg, p1 = p0 + 1;
            if (p0 < 36) {
                r0[p0] = fmaxf(acc[mi][ni][0] * sc0 + bi0, 0.f);
                r1[p0] = fmaxf(acc[mi][ni][2] * sc1 + bi1, 0.f);
            }
            if (p1 < 36) {
                r0[p1] = fmaxf(acc[mi][ni][1] * sc0 + bi0, 0.f);
                r1[p1] = fmaxf(acc[mi][ni][3] * sc1 + bi1, 0.f);
            }
        }
    }
}

// =====================================================================
// Kernel 2: catconv9 (192->128) + BN + ReLU via tf32 MMA.
// grid 6144/4, block 256 = 8 warps; 4 samples, 2 warps per sample (m-halves).
// =====================================================================
__global__ __launch_bounds__(256, 1) void catconv_mma(
    const float* __restrict__ cat_g, const float* __restrict__ cat_b,
    const float* __restrict__ cat_m, const float* __restrict__ cat_v)
{
    __shared__ uint32_t Ws[72 * 136];           // [(c_local*9+t)][o], stride 136 (≡8 mod 32)
    __shared__ uint32_t Xs[4 * 8 * 44 + 8];

    const int n0    = blockIdx.x * 4;
    const int tid   = threadIdx.x;
    const int warp  = tid >> 5;
    const int lane  = tid & 31;
    const int group = lane >> 2;
    const int tg    = lane & 3;
    const int smp   = warp >> 1;
    const int mh    = (warp & 1) * 64;

    for (int i = tid; i < 4 * 8 * 44 + 8; i += 256) Xs[i] = 0u;

    float acc[4][5][4];
#pragma unroll
    for (int mi = 0; mi < 4; mi++)
#pragma unroll
        for (int ni = 0; ni < 5; ni++)
#pragma unroll
            for (int j = 0; j < 4; j++) acc[mi][ni][j] = 0.f;

    for (int cb = 0; cb < 192; cb += 8) {
        __syncthreads();
        {
            const uint32_t* src = &g_wcat[(cb * 9) * 128];
            for (int i = tid; i < 72 * 128; i += 256) {
                int row = i >> 7, o = i & 127;
                Ws[row * 136 + o] = src[i];
            }
        }
        for (int i = tid; i < 4 * 8 * 36; i += 256) {
            int sm = i / 288;
            int r  = i - sm * 288;
            int ci = r / 36;
            int s  = r - ci * 36;
            Xs[(sm * 8 + ci) * 44 + 4 + s] =
                f2tf(g_cat[(((size_t)(n0 + sm)) * 192 + cb + ci) * 36 + s]);
        }
        __syncthreads();

#pragma unroll
        for (int t = 0; t < 9; t++) {
            uint32_t a[4][4];
#pragma unroll
            for (int mi = 0; mi < 4; mi++) {
                int o = mh + mi * 16 + group;
                a[mi][0] = Ws[(tg * 9 + t) * 136 + o];
                a[mi][1] = Ws[(tg * 9 + t) * 136 + o + 8];
                a[mi][2] = Ws[((tg + 4) * 9 + t) * 136 + o];
                a[mi][3] = Ws[((tg + 4) * 9 + t) * 136 + o + 8];
            }
            uint32_t b[5][2];
#pragma unroll
            for (int ni = 0; ni < 5; ni++) {
                int idx = (smp * 8 + tg) * 44 + ni * 8 + group + t;
                b[ni][0] = Xs[idx];
                b[ni][1] = Xs[idx + 4 * 44];
            }
#pragma unroll
            for (int mi = 0; mi < 4; mi++)
#pragma unroll
                for (int ni = 0; ni < 5; ni++)
                    mma_tf32(acc[mi][ni], a[mi], b[ni]);
        }
    }

#pragma unroll
    for (int mi = 0; mi < 4; mi++) {
        int o0 = mh + mi * 16 + group;
        int o1 = o0 + 8;
        float sc0 = cat_g[o0] * rsqrtf(cat_v[o0] + EPS);
        float bi0 = cat_b[o0] - cat_m[o0] * sc0;
        float sc1 = cat_g[o1] * rsqrtf(cat_v[o1] + EPS);
        float bi1 = cat_b[o1] - cat_m[o1] * sc1;
        float* r0 = &g_catout[(((size_t)(n0 + smp)) * 128 + o0) * 36];
        float* r1 = &g_catout[(((size_t)(n0 + smp)) * 128 + o1) * 36];
#pragma unroll
        for (int ni = 0; ni < 5; ni++) {
            int p0 = ni * 8 + 2 * tg, p1 = p0 + 1;
            if (p0 < 36) {
                r0[p0] = fmaxf(acc[mi][ni][0] * sc0 + bi0, 0.f);
                r1[p0] = fmaxf(acc[mi][ni][2] * sc1 + bi1, 0.f);
            }
            if (p1 < 36) {
                r0[p1] = fmaxf(acc[mi][ni][1] * sc0 + bi0, 0.f);
                r1[p1] = fmaxf(acc[mi][ni][3] * sc1 + bi1, 0.f);
            }
        }
    }
}

// =====================================================================
// Kernel 3: fc GEMM M=6144,N=128,K=4608 via tf32 MMA; writes h+bias to g_roi.
// grid 96, block 256; block tile M=64 x N=128; warp tile 32x32.
// (LayerNorm folded into attn kernel.)
// =====================================================================
__global__ __launch_bounds__(256, 1) void fc_mma(
    const float* __restrict__ fc_w, const float* __restrict__ fc_b)
{
    __shared__ uint32_t As[64 * 36];
    __shared__ uint32_t Bs[128 * 36];

    const int mb    = blockIdx.x * 64;
    const int tid   = threadIdx.x;
    const int warp  = tid >> 5;
    const int lane  = tid & 31;
    const int group = lane >> 2;
    const int tg    = lane & 3;
    const int wm    = (warp >> 2) * 32;
    const int wn    = (warp & 3) * 32;

    float acc[2][4][4];
#pragma unroll
    for (int mi = 0; mi < 2; mi++)
#pragma unroll
        for (int ni = 0; ni < 4; ni++)
#pragma unroll
            for (int j = 0; j < 4; j++) acc[mi][ni][j] = 0.f;

    for (int kk = 0; kk < KTOT; kk += 32) {
        __syncthreads();
        for (int i = tid; i < 64 * 32; i += 256) {
            int m = i >> 5, k = i & 31;
            As[m * 36 + k] = f2tf(g_catout[((size_t)(mb + m)) * KTOT + kk + k]);
        }
        for (int i = tid; i < 128 * 32; i += 256) {
            int f = i >> 5, k = i & 31;
            Bs[f * 36 + k] = f2tf(fc_w[(size_t)f * KTOT + kk + k]);
        }
        __syncthreads();

#pragma unroll
        for (int kb = 0; kb < 32; kb += 8) {
            uint32_t a[2][4];
#pragma unroll
            for (int mi = 0; mi < 2; mi++) {
                int m = wm + mi * 16 + group;
                a[mi][0] = As[m * 36 + kb + tg];
                a[mi][1] = As[(m + 8) * 36 + kb + tg];
                a[mi][2] = As[m * 36 + kb + tg + 4];
                a[mi][3] = As[(m + 8) * 36 + kb + tg + 4];
            }
            uint32_t b[4][2];
#pragma unroll
            for (int ni = 0; ni < 4; ni++) {
                int n = wn + ni * 8 + group;
                b[ni][0] = Bs[n * 36 + kb + tg];
                b[ni][1] = Bs[n * 36 + kb + tg + 4];
            }
#pragma unroll
            for (int mi = 0; mi < 2; mi++)
#pragma unroll
                for (int ni = 0; ni < 4; ni++)
                    mma_tf32(acc[mi][ni], a[mi], b[ni]);
        }
    }

#pragma unroll
    for (int mi = 0; mi < 2; mi++) {
        int m = wm + mi * 16 + group;
#pragma unroll
        for (int ni = 0; ni < 4; ni++) {
            int n = wn + ni * 8 + 2 * tg;
            g_roi[((size_t)(mb + m)) * 128 + n]         = acc[mi][ni][0] + fc_b[n];
            g_roi[((size_t)(mb + m)) * 128 + n + 1]     = acc[mi][ni][1] + fc_b[n + 1];
            g_roi[((size_t)(mb + m + 8)) * 128 + n]     = acc[mi][ni][2] + fc_b[n];
            g_roi[((size_t)(mb + m + 8)) * 128 + n + 1] = acc[mi][ni][3] + fc_b[n + 1];
        }
    }
}

// =====================================================================
// Kernel 4: key/val at the 250 nearest-subsampled points (fp32, unchanged).
// =====================================================================
__global__ __launch_bounds__(256) void keyval_kernel(
    const float* __restrict__ fmap,
    const float* __restrict__ key_w, const float* __restrict__ key_g, const float* __restrict__ key_beta,
    const float* __restrict__ key_m, const float* __restrict__ key_v,
    const float* __restrict__ val_w, const float* __restrict__ val_b)
{
    __shared__ float Xs[128][26];

    const int b   = blockIdx.x;
    const int l0  = blockIdx.y * 25;
    const int tid = threadIdx.x;

    for (int i = tid; i < 128 * 25; i += 256) {
        int c = i / 25;
        int l = i - c * 25;
        int L = l0 + l;
        int h = (L / 25) * 4;
        int w = (L % 25) * 4;
        Xs[c][l] = fmap[(((size_t)b * 128 + c) * 40 + h) * 100 + w];
    }
    __syncthreads();

    const int o     = tid & 127;
    const int which = tid >> 7;
    const float* W  = which ? val_w : key_w;
    float sc, bi;
    if (which == 0) {
        sc = key_g[o] * rsqrtf(key_v[o] + EPS);
        bi = key_beta[o] - key_m[o] * sc;
    } else {
        sc = 1.f;
        bi = val_b[o];
    }

    float acc[25];
#pragma unroll
    for (int l = 0; l < 25; l++) acc[l] = 0.f;
    for (int c = 0; c < 128; c++) {
        float w = W[o * 128 + c];
#pragma unroll
        for (int l = 0; l < 25; l++) acc[l] += w * Xs[c][l];
    }

    if (which == 0) {
        for (int l = 0; l < 25; l++) {
            float vv = acc[l] * sc + bi;
            g_k[((size_t)b * L250 + l0 + l) * 128 + o] = vv > 0.f ? vv : 0.f;
        }
    } else {
        for (int l = 0; l < 25; l++) {
            g_v[((size_t)b * L250 + l0 + l) * 128 + o] = acc[l] + bi;
        }
    }
}

// =====================================================================
// Kernel 5: LN + ReLU (folded) + attention + gate + residual.
// grid (192, 32), block 256.
// =====================================================================
__global__ __launch_bounds__(256) void attn_kernel(
    const float* __restrict__ ln_g, const float* __restrict__ ln_b,
    const float* __restrict__ q_w, const float* __restrict__ q_b,
    const float* __restrict__ gate_w, const float* __restrict__ gate_b,
    float* __restrict__ out)
{
    __shared__ float qs[128];
    __shared__ float ros[128];
    __shared__ float sc[256];
    __shared__ float red[16];
    __shared__ float lnred[8];
    __shared__ float ctxs[2][128];

    const int n   = blockIdx.x;
    const int b   = blockIdx.y;
    const int tid = threadIdx.x;
    const int warp = tid >> 5;
    const int lane = tid & 31;
    const size_t row = ((size_t)b * NP + n) * 128;

    // ---- LayerNorm over the 128-wide row (pre-LN h in g_roi) ----
    float hv = (tid < 128) ? g_roi[row + tid] : 0.f;
    float s = (tid < 128) ? hv : 0.f;
#pragma unroll
    for (int off = 16; off > 0; off >>= 1) s += __shfl_xor_sync(0xffffffffu, s, off);
    if (lane == 0 && warp < 4) lnred[warp] = s;
    __syncthreads();
    const float mu = (lnred[0] + lnred[1] + lnred[2] + lnred[3]) * (1.f / 128.f);
    const float d  = hv - mu;
    float s2 = (tid < 128) ? d * d : 0.f;
#pragma unroll
    for (int off = 16; off > 0; off >>= 1) s2 += __shfl_xor_sync(0xffffffffu, s2, off);
    __syncthreads();
    if (lane == 0 && warp < 4) lnred[warp] = s2;
    __syncthreads();
    const float var = (lnred[0] + lnred[1] + lnred[2] + lnred[3]) * (1.f / 128.f);
    const float inv_std = rsqrtf(var + EPS);

    if (tid < 128) {
        float r = d * inv_std * ln_g[tid] + ln_b[tid];
        r = fmaxf(r, 0.f);
        ros[tid] = r;
        float qq = r * q_w[n] + q_b[n];
        qs[tid] = fmaxf(qq, 0.f);
    }
    __syncthreads();

    // ---- scores q.k / sqrt(C) ----
    const float scale = 0.08838834764831845f;   // 128^-0.5
    for (int l = warp; l < L250; l += 8) {
        const float* kp = &g_k[((size_t)b * L250 + l) * 128];
        float dd = 0.f;
#pragma unroll
        for (int c0 = 0; c0 < 128; c0 += 32) dd += qs[c0 + lane] * kp[c0 + lane];
#pragma unroll
        for (int off = 16; off > 0; off >>= 1) dd += __shfl_xor_sync(0xffffffffu, dd, off);
        if (lane == 0) sc[l] = dd * scale;
    }
    __syncthreads();

    // ---- softmax ----
    float m = -1e30f;
    for (int l = tid; l < L250; l += 256) m = fmaxf(m, sc[l]);
#pragma unroll
    for (int off = 16; off > 0; off >>= 1) m = fmaxf(m, __shfl_xor_sync(0xffffffffu, m, off));
    if (lane == 0) red[warp] = m;
    __syncthreads();
    if (tid < 8) {
        float mm = red[tid];
#pragma unroll
        for (int off = 4; off > 0; off >>= 1) mm = fmaxf(mm, __shfl_xor_sync(0xffu, mm, off));
        if (tid == 0) red[0] = mm;
    }
    __syncthreads();
    m = red[0];

    float ssum = 0.f;
    for (int l = tid; l < L250; l += 256) {
        float e = __expf(sc[l] - m);
        sc[l] = e;
        ssum += e;
    }
#pragma unroll
    for (int off = 16; off > 0; off >>= 1) ssum += __shfl_xor_sync(0xffffffffu, ssum, off);
    if (lane == 0) red[8 + warp] = ssum;
    __syncthreads();
    if (tid < 8) {
        float ss = red[8 + tid];
#pragma unroll
        for (int off = 4; off > 0; off >>= 1) ss += __shfl_xor_sync(0xffu, ss, off);
        if (tid == 0) red[8] = ss;
    }
    __syncthreads();
    const float inv = 1.f / red[8];

    // ---- ctx = softmax . v ----
    const int c    = tid & 127;
    const int half = tid >> 7;
    float a = 0.f;
    for (int l = half; l < L250; l += 2)
        a += sc[l] * g_v[((size_t)b * L250 + l) * 128 + c];
    ctxs[half][c] = a;
    __syncthreads();

    if (tid < 128) {
        float ctx = (ctxs[0][tid] + ctxs[1][tid]) * inv;
        out[row + tid] = ros[tid] + ctx * gate_w[n] + gate_b[n];
    }
}

// =====================================================================
extern "C" void kernel_launch(void* const* d_in, const int* in_sizes, int n_in,
                              void* d_out, int out_size)
{
    const float* roi0   = (const float*)d_in[0];
    const float* roi1   = (const float*)d_in[1];
    const float* roi2   = (const float*)d_in[2];
    const float* fmap   = (const float*)d_in[3];
    const float* conv_w = (const float*)d_in[4];
    const float* conv_g = (const float*)d_in[5];
    const float* conv_b = (const float*)d_in[6];
    const float* conv_m = (const float*)d_in[7];
    const float* conv_v = (const float*)d_in[8];
    const float* cat_w  = (const float*)d_in[9];
    const float* cat_g  = (const float*)d_in[10];
    const float* cat_b  = (const float*)d_in[11];
    const float* cat_m  = (const float*)d_in[12];
    const float* cat_v  = (const float*)d_in[13];
    const float* fc_w   = (const float*)d_in[14];
    const float* fc_b   = (const float*)d_in[15];
    const float* ln_g   = (const float*)d_in[16];
    const float* ln_b   = (const float*)d_in[17];
    const float* key_w  = (const float*)d_in[18];
    const float* key_g  = (const float*)d_in[19];
    const float* key_be = (const float*)d_in[20];
    const float* key_m  = (const float*)d_in[21];
    const float* key_v  = (const float*)d_in[22];
    const float* q_w    = (const float*)d_in[23];
    const float* q_b    = (const float*)d_in[24];
    const float* val_w  = (const float*)d_in[25];
    const float* val_b  = (const float*)d_in[26];
    const float* gate_w = (const float*)d_in[27];
    const float* gate_b = (const float*)d_in[28];

    float* out = (float*)d_out;

    prep_w_kernel<<<(3 * 128 * 9 * 64 + 255) / 256, 256>>>(conv_w, cat_w);
    conv_level_mma<<<dim3(NSAMP / 8, 3), 256>>>(roi0, roi1, roi2,
                                                conv_g, conv_b, conv_m, conv_v);
    catconv_mma<<<NSAMP / 4, 256>>>(cat_g, cat_b, cat_m, cat_v);
    fc_mma<<<NSAMP / 64, 256>>>(fc_w, fc_b);
    keyval_kernel<<<dim3(BB, 10), 256>>>(fmap, key_w, key_g, key_be, key_m, key_v, val_w, val_b);
    attn_kernel<<<dim3(NP, BB), 256>>>(ln_g, ln_b, q_w, q_b, gate_w, gate_b, out);
}

// round 11
// speedup vs baseline: 3.5933x; 2.4734x over previous
#include <cuda_runtime.h>
#include <cuda_bf16.h>
#include <math.h>
#include <stdint.h>

// ---------------- problem constants ----------------
#define BB     32
#define NP     192
#define CC     128
#define NS     36
#define MID    64
#define FCH    128
#define NSAMP  (BB * NP)        // 6144
#define KTOT   (CC * NS)        // 4608
#define L250   250
#define EPS    1e-5f

// ---------------- scratch (device globals; no allocation allowed) ----------------
__device__ float g_cat[(size_t)NSAMP * 192 * NS];     // concat of 3 level-conv outputs (tf32-valued)
__device__ float g_catout[(size_t)NSAMP * CC * NS];   // catconv output (tf32-valued)
__device__ float g_roi[(size_t)NSAMP * FCH];          // fc output h (pre-LN)
__device__ float g_k[(size_t)BB * L250 * CC];         // key (b,l,c)
__device__ float g_v[(size_t)BB * L250 * CC];         // val (b,l,c)
// pre-transposed / pre-converted tf32 weights
__device__ uint32_t g_wlvl[3 * 128 * 9 * 64];         // [(c*9+t)][o] per level
__device__ uint32_t g_wcat[192 * 9 * 128];            // [(c*9+t)][o]
__device__ uint32_t g_wfc[(size_t)FCH * KTOT];        // [o][k] (same layout as fc_w)

// ---------------- tf32 / cp.async helpers ----------------
__device__ __forceinline__ uint32_t f2tf(float f) {
    uint32_t u;
    asm("cvt.rna.tf32.f32 %0, %1;" : "=r"(u) : "f"(f));
    return u;
}

__device__ __forceinline__ void mma_tf32(float c[4], const uint32_t a[4], const uint32_t b[2]) {
    asm volatile(
        "mma.sync.aligned.m16n8k8.row.col.f32.tf32.tf32.f32 "
        "{%0,%1,%2,%3}, {%4,%5,%6,%7}, {%8,%9}, {%0,%1,%2,%3};\n"
        : "+f"(c[0]), "+f"(c[1]), "+f"(c[2]), "+f"(c[3])
        : "r"(a[0]), "r"(a[1]), "r"(a[2]), "r"(a[3]), "r"(b[0]), "r"(b[1]));
}

__device__ __forceinline__ void cpasync16(uint32_t dst_smem, const void* src) {
    asm volatile("cp.async.ca.shared.global [%0], [%1], 16;\n" :: "r"(dst_smem), "l"(src));
}
#define CP_COMMIT() asm volatile("cp.async.commit_group;\n" ::: "memory")
#define CP_WAIT1()  asm volatile("cp.async.wait_group 1;\n" ::: "memory")
#define CP_WAIT0()  asm volatile("cp.async.wait_group 0;\n" ::: "memory")

// =====================================================================
// Kernel 0: one-time weight transpose + tf32 convert.
// =====================================================================
__global__ __launch_bounds__(256) void prep_w_kernel(
    const float* __restrict__ conv_w, const float* __restrict__ cat_w,
    const float* __restrict__ fc_w)
{
    int i = blockIdx.x * 256 + threadIdx.x;
    if (i < 3 * 128 * 9 * 64) {
        int lvl = i / (128 * 9 * 64);
        int r   = i - lvl * (128 * 9 * 64);
        int row = r >> 6;           // c*9 + t
        int o   = r & 63;
        int c   = row / 9, t = row - c * 9;
        g_wlvl[i] = f2tf(conv_w[((lvl * 64 + o) * 128 + c) * 9 + t]);
    }
    if (i < 192 * 9 * 128) {
        int row = i >> 7;           // c*9 + t
        int o   = i & 127;
        int c   = row / 9, t = row - c * 9;
        g_wcat[i] = f2tf(cat_w[(o * 192 + c) * 9 + t]);
    }
    if (i < FCH * KTOT) {
        g_wfc[i] = f2tf(fc_w[i]);
    }
}

// =====================================================================
// Kernel 1: per-level conv9 (128->64) + BN + ReLU via tf32 MMA.
// 2-stage cp.async double buffering. grid (768,3), block 256 (8 warps,
// 1 sample/warp). Epilogue stores tf32-rounded values.
// =====================================================================
__global__ __launch_bounds__(256, 2) void conv_level_mma(
    const float* __restrict__ x0, const float* __restrict__ x1, const float* __restrict__ x2,
    const float* __restrict__ conv_g, const float* __restrict__ conv_b,
    const float* __restrict__ conv_m, const float* __restrict__ conv_v)
{
    __shared__ uint32_t Ws[2][72 * 72];           // [(c_local*9+t)][o], stride 72
    __shared__ uint32_t Xs[2][8 * 8 * 44 + 8];    // [smp][c_local][44], stride 44

    const int lvl   = blockIdx.y;
    const int n0    = blockIdx.x * 8;
    const float* __restrict__ x = (lvl == 0) ? x0 : ((lvl == 1) ? x1 : x2);
    const int tid   = threadIdx.x;
    const int warp  = tid >> 5;
    const int lane  = tid & 31;
    const int group = lane >> 2;
    const int tg    = lane & 3;
    const int smp   = warp;

    // zero halos + tail of both stages once (cp.async only writes interior cols 4..39)
    for (int st = 0; st < 2; st++) {
        for (int i = tid; i < 8 * 8 * 8 + 8; i += 256) {
            if (i < 512) {
                int sm = i >> 6, r = i & 63, ci = r >> 3, p = r & 7;
                int pp = (p < 4) ? p : (36 + p);
                Xs[st][(sm * 8 + ci) * 44 + pp] = 0u;
            } else {
                Xs[st][8 * 8 * 44 + (i - 512)] = 0u;
            }
        }
    }

    const uint32_t* __restrict__ wl = &g_wlvl[lvl * (128 * 9 * 64)];

    auto issue_chunk = [&](int c) {
        const int st = c & 1;
        const int cb = c * 8;
        uint32_t wbase = (uint32_t)__cvta_generic_to_shared(&Ws[st][0]);
        uint32_t xbase = (uint32_t)__cvta_generic_to_shared(&Xs[st][0]);
        const uint32_t* wsrc = wl + cb * 576;     // chunk is contiguous 72x64
        for (int i = tid; i < 1152; i += 256) {
            int row = i >> 4, q = i & 15;
            cpasync16(wbase + (uint32_t)(row * 72 + q * 4) * 4u, wsrc + row * 64 + q * 4);
        }
        for (int i = tid; i < 576; i += 256) {
            int sm = i / 72;
            int r  = i - sm * 72;
            int ci = r / 9;
            int q  = r - ci * 9;
            cpasync16(xbase + (uint32_t)((sm * 8 + ci) * 44 + 4 + q * 4) * 4u,
                      x + (((size_t)(n0 + sm)) * 128 + cb + ci) * 36 + q * 4);
        }
    };

    float acc[4][5][4];
#pragma unroll
    for (int mi = 0; mi < 4; mi++)
#pragma unroll
        for (int ni = 0; ni < 5; ni++)
#pragma unroll
            for (int j = 0; j < 4; j++) acc[mi][ni][j] = 0.f;

    issue_chunk(0);
    CP_COMMIT();

    for (int c = 0; c < 16; c++) {
        if (c + 1 < 16) { issue_chunk(c + 1); CP_COMMIT(); CP_WAIT1(); }
        else            { CP_WAIT0(); }
        __syncthreads();
        const int st = c & 1;

#pragma unroll
        for (int t = 0; t < 9; t++) {
            uint32_t a[4][4];
#pragma unroll
            for (int mi = 0; mi < 4; mi++) {
                int o = mi * 16 + group;
                a[mi][0] = Ws[st][(tg * 9 + t) * 72 + o];
                a[mi][1] = Ws[st][(tg * 9 + t) * 72 + o + 8];
                a[mi][2] = Ws[st][((tg + 4) * 9 + t) * 72 + o];
                a[mi][3] = Ws[st][((tg + 4) * 9 + t) * 72 + o + 8];
            }
            uint32_t b[5][2];
#pragma unroll
            for (int ni = 0; ni < 5; ni++) {
                int idx = (smp * 8 + tg) * 44 + ni * 8 + group + t;
                b[ni][0] = f2tf(__uint_as_float(Xs[st][idx]));
                b[ni][1] = f2tf(__uint_as_float(Xs[st][idx + 4 * 44]));
            }
#pragma unroll
            for (int mi = 0; mi < 4; mi++)
#pragma unroll
                for (int ni = 0; ni < 5; ni++)
                    mma_tf32(acc[mi][ni], a[mi], b[ni]);
        }
        __syncthreads();
    }

    // epilogue: BN + ReLU, tf32-rounded store -> g_cat
#pragma unroll
    for (int mi = 0; mi < 4; mi++) {
        int o0  = mi * 16 + group;
        int gc0 = lvl * 64 + o0, gc1 = gc0 + 8;
        float sc0 = conv_g[gc0] * rsqrtf(conv_v[gc0] + EPS);
        float bi0 = conv_b[gc0] - conv_m[gc0] * sc0;
        float sc1 = conv_g[gc1] * rsqrtf(conv_v[gc1] + EPS);
        float bi1 = conv_b[gc1] - conv_m[gc1] * sc1;
        float* r0 = &g_cat[(((size_t)(n0 + smp)) * 192 + gc0) * 36];
        float* r1 = &g_cat[(((size_t)(n0 + smp)) * 192 + gc1) * 36];
#pragma unroll
        for (int ni = 0; ni < 5; ni++) {
            int p0 = ni * 8 + 2 * tg, p1 = p0 + 1;
            if (p0 < 36) {
                r0[p0] = __uint_as_float(f2tf(fmaxf(acc[mi][ni][0] * sc0 + bi0, 0.f)));
                r1[p0] = __uint_as_float(f2tf(fmaxf(acc[mi][ni][2] * sc1 + bi1, 0.f)));
            }
            if (p1 < 36) {
                r0[p1] = __uint_as_float(f2tf(fmaxf(acc[mi][ni][1] * sc0 + bi0, 0.f)));
                r1[p1] = __uint_as_float(f2tf(fmaxf(acc[mi][ni][3] * sc1 + bi1, 0.f)));
            }
        }
    }
}

// =====================================================================
// Kernel 2: catconv9 (192->128) + BN + ReLU via tf32 MMA, cp.async x2.
// grid 1536, block 256; 4 samples, 2 warps/sample (m-halves).
// Inputs in g_cat are already tf32-valued -> no cvt in fragments.
// =====================================================================
__global__ __launch_bounds__(256, 2) void catconv_mma(
    const float* __restrict__ cat_g, const float* __restrict__ cat_b,
    const float* __restrict__ cat_m, const float* __restrict__ cat_v)
{
    __shared__ uint32_t Ws[2][72 * 136];
    __shared__ uint32_t Xs[2][4 * 8 * 44 + 8];

    const int n0    = blockIdx.x * 4;
    const int tid   = threadIdx.x;
    const int warp  = tid >> 5;
    const int lane  = tid & 31;
    const int group = lane >> 2;
    const int tg    = lane & 3;
    const int smp   = warp >> 1;
    const int mh    = (warp & 1) * 64;

    for (int st = 0; st < 2; st++) {
        for (int i = tid; i < 4 * 8 * 8 + 8; i += 256) {
            if (i < 256) {
                int sm = i >> 6, r = i & 63, ci = r >> 3, p = r & 7;
                int pp = (p < 4) ? p : (36 + p);
                Xs[st][(sm * 8 + ci) * 44 + pp] = 0u;
            } else {
                Xs[st][4 * 8 * 44 + (i - 256)] = 0u;
            }
        }
    }

    auto issue_chunk = [&](int c) {
        const int st = c & 1;
        const int cb = c * 8;
        uint32_t wbase = (uint32_t)__cvta_generic_to_shared(&Ws[st][0]);
        uint32_t xbase = (uint32_t)__cvta_generic_to_shared(&Xs[st][0]);
        const uint32_t* wsrc = &g_wcat[cb * 9 * 128];   // contiguous 72x128
        for (int i = tid; i < 2304; i += 256) {
            int row = i >> 5, q = i & 31;
            cpasync16(wbase + (uint32_t)(row * 136 + q * 4) * 4u, wsrc + row * 128 + q * 4);
        }
        for (int i = tid; i < 288; i += 256) {
            if (i < 288) {
                int sm = i / 72;
                int r  = i - sm * 72;
                int ci = r / 9;
                int q  = r - ci * 9;
                cpasync16(xbase + (uint32_t)((sm * 8 + ci) * 44 + 4 + q * 4) * 4u,
                          &g_cat[(((size_t)(n0 + sm)) * 192 + cb + ci) * 36 + q * 4]);
            }
        }
    };

    float acc[4][5][4];
#pragma unroll
    for (int mi = 0; mi < 4; mi++)
#pragma unroll
        for (int ni = 0; ni < 5; ni++)
#pragma unroll
            for (int j = 0; j < 4; j++) acc[mi][ni][j] = 0.f;

    issue_chunk(0);
    CP_COMMIT();

    for (int c = 0; c < 24; c++) {
        if (c + 1 < 24) { issue_chunk(c + 1); CP_COMMIT(); CP_WAIT1(); }
        else            { CP_WAIT0(); }
        __syncthreads();
        const int st = c & 1;

#pragma unroll
        for (int t = 0; t < 9; t++) {
            uint32_t a[4][4];
#pragma unroll
            for (int mi = 0; mi < 4; mi++) {
                int o = mh + mi * 16 + group;
                a[mi][0] = Ws[st][(tg * 9 + t) * 136 + o];
                a[mi][1] = Ws[st][(tg * 9 + t) * 136 + o + 8];
                a[mi][2] = Ws[st][((tg + 4) * 9 + t) * 136 + o];
                a[mi][3] = Ws[st][((tg + 4) * 9 + t) * 136 + o + 8];
            }
            uint32_t b[5][2];
#pragma unroll
            for (int ni = 0; ni < 5; ni++) {
                int idx = (smp * 8 + tg) * 44 + ni * 8 + group + t;
                b[ni][0] = Xs[st][idx];
                b[ni][1] = Xs[st][idx + 4 * 44];
            }
#pragma unroll
            for (int mi = 0; mi < 4; mi++)
#pragma unroll
                for (int ni = 0; ni < 5; ni++)
                    mma_tf32(acc[mi][ni], a[mi], b[ni]);
        }
        __syncthreads();
    }

#pragma unroll
    for (int mi = 0; mi < 4; mi++) {
        int o0 = mh + mi * 16 + group;
        int o1 = o0 + 8;
        float sc0 = cat_g[o0] * rsqrtf(cat_v[o0] + EPS);
        float bi0 = cat_b[o0] - cat_m[o0] * sc0;
        float sc1 = cat_g[o1] * rsqrtf(cat_v[o1] + EPS);
        float bi1 = cat_b[o1] - cat_m[o1] * sc1;
        float* r0 = &g_catout[(((size_t)(n0 + smp)) * 128 + o0) * 36];
        float* r1 = &g_catout[(((size_t)(n0 + smp)) * 128 + o1) * 36];
#pragma unroll
        for (int ni = 0; ni < 5; ni++) {
            int p0 = ni * 8 + 2 * tg, p1 = p0 + 1;
            if (p0 < 36) {
                r0[p0] = __uint_as_float(f2tf(fmaxf(acc[mi][ni][0] * sc0 + bi0, 0.f)));
                r1[p0] = __uint_as_float(f2tf(fmaxf(acc[mi][ni][2] * sc1 + bi1, 0.f)));
            }
            if (p1 < 36) {
                r0[p1] = __uint_as_float(f2tf(fmaxf(acc[mi][ni][1] * sc0 + bi0, 0.f)));
                r1[p1] = __uint_as_float(f2tf(fmaxf(acc[mi][ni][3] * sc1 + bi1, 0.f)));
            }
        }
    }
}

// =====================================================================
// Kernel 3: fc GEMM M=6144,N=128,K=4608 via tf32 MMA, cp.async x2.
// grid 192 (M-tile 32), block 256; warp tile 16x32 (2m x 4n warps).
// A (g_catout) and B (g_wfc) are tf32-valued -> no cvt in fragments.
// =====================================================================
__global__ __launch_bounds__(256, 2) void fc_mma(const float* __restrict__ fc_b)
{
    __shared__ uint32_t As[2][32 * 36];
    __shared__ uint32_t Bs[2][128 * 36];

    const int mb    = blockIdx.x * 32;
    const int tid   = threadIdx.x;
    const int warp  = tid >> 5;
    const int lane  = tid & 31;
    const int group = lane >> 2;
    const int tg    = lane & 3;
    const int wm    = (warp >> 2) * 16;       // 0 or 16
    const int wn    = (warp & 3) * 32;        // 0,32,64,96

    auto issue_chunk = [&](int c) {
        const int st = c & 1;
        const int kk = c * 32;
        uint32_t abase = (uint32_t)__cvta_generic_to_shared(&As[st][0]);
        uint32_t bbase = (uint32_t)__cvta_generic_to_shared(&Bs[st][0]);
        for (int i = tid; i < 256; i += 256) {
            int m = i >> 3, q = i & 7;
            cpasync16(abase + (uint32_t)(m * 36 + q * 4) * 4u,
                      &g_catout[((size_t)(mb + m)) * KTOT + kk + q * 4]);
        }
        for (int i = tid; i < 1024; i += 256) {
            int f = i >> 3, q = i & 7;
            cpasync16(bbase + (uint32_t)(f * 36 + q * 4) * 4u,
                      &g_wfc[(size_t)f * KTOT + kk + q * 4]);
        }
    };

    float acc[4][4];
#pragma unroll
    for (int ni = 0; ni < 4; ni++)
#pragma unroll
        for (int j = 0; j < 4; j++) acc[ni][j] = 0.f;

    issue_chunk(0);
    CP_COMMIT();

    for (int c = 0; c < KTOT / 32; c++) {
        if (c + 1 < KTOT / 32) { issue_chunk(c + 1); CP_COMMIT(); CP_WAIT1(); }
        else                   { CP_WAIT0(); }
        __syncthreads();
        const int st = c & 1;

#pragma unroll
        for (int kb = 0; kb < 32; kb += 8) {
            uint32_t a[4];
            {
                int m = wm + group;
                a[0] = As[st][m * 36 + kb + tg];
                a[1] = As[st][(m + 8) * 36 + kb + tg];
                a[2] = As[st][m * 36 + kb + tg + 4];
                a[3] = As[st][(m + 8) * 36 + kb + tg + 4];
            }
            uint32_t b[4][2];
#pragma unroll
            for (int ni = 0; ni < 4; ni++) {
                int n = wn + ni * 8 + group;
                b[ni][0] = Bs[st][n * 36 + kb + tg];
                b[ni][1] = Bs[st][n * 36 + kb + tg + 4];
            }
#pragma unroll
            for (int ni = 0; ni < 4; ni++)
                mma_tf32(acc[ni], a, b[ni]);
        }
        __syncthreads();
    }

    {
        int m = mb + wm + group;
#pragma unroll
        for (int ni = 0; ni < 4; ni++) {
            int n = wn + ni * 8 + 2 * tg;
            g_roi[(size_t)m * 128 + n]           = acc[ni][0] + fc_b[n];
            g_roi[(size_t)m * 128 + n + 1]       = acc[ni][1] + fc_b[n + 1];
            g_roi[(size_t)(m + 8) * 128 + n]     = acc[ni][2] + fc_b[n];
            g_roi[(size_t)(m + 8) * 128 + n + 1] = acc[ni][3] + fc_b[n + 1];
        }
    }
}

// =====================================================================
// Kernel 4: key/val at the 250 nearest-subsampled points (fp32).
// =====================================================================
__global__ __launch_bounds__(256) void keyval_kernel(
    const float* __restrict__ fmap,
    const float* __restrict__ key_w, const float* __restrict__ key_g, const float* __restrict__ key_beta,
    const float* __restrict__ key_m, const float* __restrict__ key_v,
    const float* __restrict__ val_w, const float* __restrict__ val_b)
{
    __shared__ float Xs[128][26];

    const int b   = blockIdx.x;
    const int l0  = blockIdx.y * 25;
    const int tid = threadIdx.x;

    for (int i = tid; i < 128 * 25; i += 256) {
        int c = i / 25;
        int l = i - c * 25;
        int L = l0 + l;
        int h = (L / 25) * 4;
        int w = (L % 25) * 4;
        Xs[c][l] = fmap[(((size_t)b * 128 + c) * 40 + h) * 100 + w];
    }
    __syncthreads();

    const int o     = tid & 127;
    const int which = tid >> 7;
    const float* W  = which ? val_w : key_w;
    float sc, bi;
    if (which == 0) {
        sc = key_g[o] * rsqrtf(key_v[o] + EPS);
        bi = key_beta[o] - key_m[o] * sc;
    } else {
        sc = 1.f;
        bi = val_b[o];
    }

    float acc[25];
#pragma unroll
    for (int l = 0; l < 25; l++) acc[l] = 0.f;
    for (int c = 0; c < 128; c++) {
        float w = W[o * 128 + c];
#pragma unroll
        for (int l = 0; l < 25; l++) acc[l] += w * Xs[c][l];
    }

    if (which == 0) {
        for (int l = 0; l < 25; l++) {
            float vv = acc[l] * sc + bi;
            g_k[((size_t)b * L250 + l0 + l) * 128 + o] = vv > 0.f ? vv : 0.f;
        }
    } else {
        for (int l = 0; l < 25; l++) {
            g_v[((size_t)b * L250 + l0 + l) * 128 + o] = acc[l] + bi;
        }
    }
}

// =====================================================================
// Kernel 5: LN + ReLU (folded) + attention + gate + residual.
// grid (192, 32), block 256.
// =====================================================================
__global__ __launch_bounds__(256) void attn_kernel(
    const float* __restrict__ ln_g, const float* __restrict__ ln_b,
    const float* __restrict__ q_w, const float* __restrict__ q_b,
    const float* __restrict__ gate_w, const float* __restrict__ gate_b,
    float* __restrict__ out)
{
    __shared__ float qs[128];
    __shared__ float ros[128];
    __shared__ float sc[256];
    __shared__ float red[16];
    __shared__ float lnred[8];
    __shared__ float ctxs[2][128];

    const int n   = blockIdx.x;
    const int b   = blockIdx.y;
    const int tid = threadIdx.x;
    const int warp = tid >> 5;
    const int lane = tid & 31;
    const size_t row = ((size_t)b * NP + n) * 128;

    // ---- LayerNorm over the 128-wide row ----
    float hv = (tid < 128) ? g_roi[row + tid] : 0.f;
    float s = (tid < 128) ? hv : 0.f;
#pragma unroll
    for (int off = 16; off > 0; off >>= 1) s += __shfl_xor_sync(0xffffffffu, s, off);
    if (lane == 0 && warp < 4) lnred[warp] = s;
    __syncthreads();
    const float mu = (lnred[0] + lnred[1] + lnred[2] + lnred[3]) * (1.f / 128.f);
    const float d  = hv - mu;
    float s2 = (tid < 128) ? d * d : 0.f;
#pragma unroll
    for (int off = 16; off > 0; off >>= 1) s2 += __shfl_xor_sync(0xffffffffu, s2, off);
    __syncthreads();
    if (lane == 0 && warp < 4) lnred[warp] = s2;
    __syncthreads();
    const float var = (lnred[0] + lnred[1] + lnred[2] + lnred[3]) * (1.f / 128.f);
    const float inv_std = rsqrtf(var + EPS);

    if (tid < 128) {
        float r = d * inv_std * ln_g[tid] + ln_b[tid];
        r = fmaxf(r, 0.f);
        ros[tid] = r;
        float qq = r * q_w[n] + q_b[n];
        qs[tid] = fmaxf(qq, 0.f);
    }
    __syncthreads();

    // ---- scores q.k / sqrt(C) ----
    const float scale = 0.08838834764831845f;
    for (int l = warp; l < L250; l += 8) {
        const float* kp = &g_k[((size_t)b * L250 + l) * 128];
        float dd = 0.f;
#pragma unroll
        for (int c0 = 0; c0 < 128; c0 += 32) dd += qs[c0 + lane] * kp[c0 + lane];
#pragma unroll
        for (int off = 16; off > 0; off >>= 1) dd += __shfl_xor_sync(0xffffffffu, dd, off);
        if (lane == 0) sc[l] = dd * scale;
    }
    __syncthreads();

    // ---- softmax ----
    float m = -1e30f;
    for (int l = tid; l < L250; l += 256) m = fmaxf(m, sc[l]);
#pragma unroll
    for (int off = 16; off > 0; off >>= 1) m = fmaxf(m, __shfl_xor_sync(0xffffffffu, m, off));
    if (lane == 0) red[warp] = m;
    __syncthreads();
    if (tid < 8) {
        float mm = red[tid];
#pragma unroll
        for (int off = 4; off > 0; off >>= 1) mm = fmaxf(mm, __shfl_xor_sync(0xffu, mm, off));
        if (tid == 0) red[0] = mm;
    }
    __syncthreads();
    m = red[0];

    float ssum = 0.f;
    for (int l = tid; l < L250; l += 256) {
        float e = __expf(sc[l] - m);
        sc[l] = e;
        ssum += e;
    }
#pragma unroll
    for (int off = 16; off > 0; off >>= 1) ssum += __shfl_xor_sync(0xffffffffu, ssum, off);
    if (lane == 0) red[8 + warp] = ssum;
    __syncthreads();
    if (tid < 8) {
        float ss = red[8 + tid];
#pragma unroll
        for (int off = 4; off > 0; off >>= 1) ss += __shfl_xor_sync(0xffu, ss, off);
        if (tid == 0) red[8] = ss;
    }
    __syncthreads();
    const float inv = 1.f / red[8];

    // ---- ctx = softmax . v ----
    const int c    = tid & 127;
    const int half = tid >> 7;
    float a = 0.f;
    for (int l = half; l < L250; l += 2)
        a += sc[l] * g_v[((size_t)b * L250 + l) * 128 + c];
    ctxs[half][c] = a;
    __syncthreads();

    if (tid < 128) {
        float ctx = (ctxs[0][tid] + ctxs[1][tid]) * inv;
        out[row + tid] = ros[tid] + ctx * gate_w[n] + gate_b[n];
    }
}

// =====================================================================
extern "C" void kernel_launch(void* const* d_in, const int* in_sizes, int n_in,
                              void* d_out, int out_size)
{
    const float* roi0   = (const float*)d_in[0];
    const float* roi1   = (const float*)d_in[1];
    const float* roi2   = (const float*)d_in[2];
    const float* fmap   = (const float*)d_in[3];
    const float* conv_w = (const float*)d_in[4];
    const float* conv_g = (const float*)d_in[5];
    const float* conv_b = (const float*)d_in[6];
    const float* conv_m = (const float*)d_in[7];
    const float* conv_v = (const float*)d_in[8];
    const float* cat_w  = (const float*)d_in[9];
    const float* cat_g  = (const float*)d_in[10];
    const float* cat_b  = (const float*)d_in[11];
    const float* cat_m  = (const float*)d_in[12];
    const float* cat_v  = (const float*)d_in[13];
    const float* fc_w   = (const float*)d_in[14];
    const float* fc_b   = (const float*)d_in[15];
    const float* ln_g   = (const float*)d_in[16];
    const float* ln_b   = (const float*)d_in[17];
    const float* key_w  = (const float*)d_in[18];
    const float* key_g  = (const float*)d_in[19];
    const float* key_be = (const float*)d_in[20];
    const float* key_m  = (const float*)d_in[21];
    const float* key_v  = (const float*)d_in[22];
    const float* q_w    = (const float*)d_in[23];
    const float* q_b    = (const float*)d_in[24];
    const float* val_w  = (const float*)d_in[25];
    const float* val_b  = (const float*)d_in[26];
    const float* gate_w = (const float*)d_in[27];
    const float* gate_b = (const float*)d_in[28];

    float* out = (float*)d_out;

    prep_w_kernel<<<(FCH * KTOT + 255) / 256, 256>>>(conv_w, cat_w, fc_w);
    conv_level_mma<<<dim3(NSAMP / 8, 3), 256>>>(roi0, roi1, roi2,
                                                conv_g, conv_b, conv_m, conv_v);
    catconv_mma<<<NSAMP / 4, 256>>>(cat_g, cat_b, cat_m, cat_v);
    fc_mma<<<NSAMP / 32, 256>>>(fc_b);
    keyval_kernel<<<dim3(BB, 10), 256>>>(fmap, key_w, key_g, key_be, key_m, key_v, val_w, val_b);
    attn_kernel<<<dim3(NP, BB), 256>>>(ln_g, ln_b, q_w, q_b, gate_w, gate_b, out);
}